// round 8
// baseline (speedup 1.0000x reference)
#include <cuda_runtime.h>
#include <cstdint>

#define NB   8
#define NP   2048
#define KNN  10
#define NPK  (NB*NP)
#define BN_SC 0.9999950000374997f   // 1/sqrt(1+1e-5)

typedef unsigned long long u64;

// ---------------- scratch (static device globals; no allocations) ----------
__device__ float g_D [(size_t)NB*NP*NP];     // 134 MB distance matrix
__device__ float g_XC[(size_t)NPK*512];      // concat(x1,x2,x3,x4) point-major
__device__ float g_P [(size_t)NPK*256];      // W_A · x   (per point)
__device__ float g_Q [(size_t)NPK*256];      // (W_B-W_A) · x
__device__ float g_xx[NPK];                  // squared norms
__device__ int   g_idx[NPK*KNN];             // knn indices
__device__ float g_pmax[16*NB*1024];         // per-128pt-block partial max of y5
__device__ float g_psum[16*NB*1024];         // per-128pt-block partial sum of y5
__device__ float g_glob[NB*2048];            // [gmax | gavg]

__device__ __forceinline__ const float* feat_ptr(const float* xext, int use_x,
                                                 int cin_off, int& ld) {
    if (use_x) { ld = 3; return xext; }
    ld = 512; return g_XC + cin_off;
}

__device__ __forceinline__ float lrelu(float y) { return y >= 0.f ? y : 0.2f*y; }
__device__ __forceinline__ float f2lo(u64 v) { return __uint_as_float((uint32_t)v); }
__device__ __forceinline__ float f2hi(u64 v) { return __uint_as_float((uint32_t)(v >> 32)); }

// packed-f32x2 8x8 micro-step on [16][128] smem panels.
#define GSTEP2(pA, pB, k)                                                     \
    {                                                                         \
        float4 a0 = *(const float4*)((pA) + (k)*128 + (ty << 2));             \
        float4 a1 = *(const float4*)((pA) + (k)*128 + 64 + (ty << 2));        \
        ulonglong2 bx = *(const ulonglong2*)((pB) + (k)*128 + (tx << 2));     \
        ulonglong2 by = *(const ulonglong2*)((pB) + (k)*128 + 64 + (tx << 2));\
        u64 bp[4] = {bx.x, bx.y, by.x, by.y};                                 \
        float av[8] = {a0.x,a0.y,a0.z,a0.w,a1.x,a1.y,a1.z,a1.w};              \
        _Pragma("unroll")                                                     \
        for (int p = 0; p < 8; p++) {                                         \
            u64 ad;                                                           \
            asm("mov.b64 %0, {%1, %1};" : "=l"(ad) : "r"(__float_as_uint(av[p]))); \
            _Pragma("unroll")                                                 \
            for (int q = 0; q < 4; q++)                                       \
                asm("fma.rn.f32x2 %0, %1, %2, %0;"                            \
                    : "+l"(acc2[p][q]) : "l"(ad), "l"(bp[q]));                \
        }                                                                     \
    }

// stage one 16x128 A-panel + 16x128 B-panel from float4 regs
#define STAGE(As, Bs)                                                         \
    {                                                                         \
        (As)[(kq4+0)*128+m0]=pa0.x; (As)[(kq4+1)*128+m0]=pa0.y;               \
        (As)[(kq4+2)*128+m0]=pa0.z; (As)[(kq4+3)*128+m0]=pa0.w;               \
        (Bs)[(kq4+0)*128+m0]=pb0.x; (Bs)[(kq4+1)*128+m0]=pb0.y;               \
        (Bs)[(kq4+2)*128+m0]=pb0.z; (Bs)[(kq4+3)*128+m0]=pb0.w;               \
        (As)[(kq4+0)*128+m1]=pa1.x; (As)[(kq4+1)*128+m1]=pa1.y;               \
        (As)[(kq4+2)*128+m1]=pa1.z; (As)[(kq4+3)*128+m1]=pa1.w;               \
        (Bs)[(kq4+0)*128+m1]=pb1.x; (Bs)[(kq4+1)*128+m1]=pb1.y;               \
        (Bs)[(kq4+2)*128+m1]=pb1.z; (Bs)[(kq4+3)*128+m1]=pb1.w;               \
    }

// ---------------- profiling-slot shim ---------------------------------------
__global__ void nop_kernel() {}

// ---------------- squared norms --------------------------------------------
__global__ void sq_kernel(const float* __restrict__ xext, int use_x, int cin_off, int C) {
    int pt = blockIdx.x*blockDim.x + threadIdx.x;
    if (pt >= NPK) return;
    int ld; const float* F = feat_ptr(xext, use_x, cin_off, ld);
    const float* r = F + (size_t)pt*ld;
    float s = 0.f;
    for (int c = 0; c < C; c++) { float v = r[c]; s = fmaf(v, v, s); }
    g_xx[pt] = s;
}

// ---------------- dist GEMM (symmetric, upper-tri blocks) -> D tiles --------
// Epilogue: stage 64-row half-tiles to smem, write (i,j) block rows directly
// and the mirrored (j,i) block (transposed read from smem). No scans here.
__global__ __launch_bounds__(256, 2)
void dist_kernel(const float* __restrict__ xext, int use_x, int cin_off, int C) {
    extern __shared__ float sm[];
    int bi = blockIdx.y, bj = blockIdx.x;
    if (bj < bi) return;                 // symmetry: skip lower triangle
    int ld; const float* F = feat_ptr(xext, use_x, cin_off, ld);
    int b  = blockIdx.z;
    int i0 = bi << 7, j0 = bj << 7;
    int tid = threadIdx.x, tx = tid & 15, ty = tid >> 4;
    const float* Fb = F + (size_t)b*NP*ld;
    u64 acc2[8][4];
    #pragma unroll
    for (int p = 0; p < 8; p++)
        #pragma unroll
        for (int q = 0; q < 4; q++) acc2[p][q] = 0ull;

    if (((ld & 3) == 0) && ((C & 15) == 0)) {
        int nch = C >> 4;
        int m0 = tid >> 2, kq4 = (tid & 3) << 2;
        int m1 = m0 + 64;
        const float* Ar0 = &Fb[(size_t)(i0 + m0)*ld];
        const float* Br0 = &Fb[(size_t)(j0 + m0)*ld];
        const float* Ar1 = &Fb[(size_t)(i0 + m1)*ld];
        const float* Br1 = &Fb[(size_t)(j0 + m1)*ld];
        float4 pa0 = *(const float4*)(Ar0 + kq4);
        float4 pb0 = *(const float4*)(Br0 + kq4);
        float4 pa1 = *(const float4*)(Ar1 + kq4);
        float4 pb1 = *(const float4*)(Br1 + kq4);
        STAGE(sm, sm + 2048)
        for (int ch = 0; ch < nch; ch++) {
            if (ch + 1 < nch) {
                int c0 = (ch + 1) << 4;
                pa0 = *(const float4*)(Ar0 + c0 + kq4);
                pb0 = *(const float4*)(Br0 + c0 + kq4);
                pa1 = *(const float4*)(Ar1 + c0 + kq4);
                pb1 = *(const float4*)(Br1 + c0 + kq4);
            }
            __syncthreads();
            float* As = sm + (ch & 1)*4096;
            float* Bs = As + 2048;
            #pragma unroll
            for (int k = 0; k < 16; k++) GSTEP2(As, Bs, k)
            if (ch + 1 < nch) {
                float* Ad = sm + ((ch & 1) ^ 1)*4096;
                float* Bd = Ad + 2048;
                STAGE(Ad, Bd)
            }
        }
    } else {
        // scalar zero-padded path (layer 0, C=3) — single chunk
        float* As = sm;
        float* Bs = sm + 2048;
        for (int c0 = 0; c0 < C; c0 += 16) {
            #pragma unroll
            for (int e = tid; e < 2048; e += 256) {
                int m = e >> 4, k = e & 15;
                float va = 0.f, vb = 0.f;
                if (c0 + k < C) {
                    va = Fb[(size_t)(i0 + m)*ld + c0 + k];
                    vb = Fb[(size_t)(j0 + m)*ld + c0 + k];
                }
                As[k*128+m] = va; Bs[k*128+m] = vb;
            }
            __syncthreads();
            #pragma unroll
            for (int k = 0; k < 16; k++) GSTEP2(As, Bs, k)
            __syncthreads();
        }
    }

    const float* xxb = g_xx + b*NP;
    float xi[8], xj[8];
    #pragma unroll
    for (int p = 0; p < 8; p++) {
        int r = (p < 4) ? ((ty << 2) + p) : (64 + (ty << 2) + p - 4);
        xi[p] = xxb[i0 + r];
    }
    #pragma unroll
    for (int q = 0; q < 8; q++) {
        int c = (q < 4) ? ((tx << 2) + q) : (64 + (tx << 2) + q - 4);
        xj[q] = xxb[j0 + c];
    }

    float* ep = sm;                      // 64 x 133 staging
    float* Db = g_D + (size_t)b*NP*NP;

    for (int pass = 0; pass < 2; pass++) {
        __syncthreads();
        #pragma unroll
        for (int p = 0; p < 4; p++) {
            int pp = pass*4 + p;
            int r  = (ty << 2) + p;
            float aq[8];
            aq[0] = f2lo(acc2[pp][0]); aq[1] = f2hi(acc2[pp][0]);
            aq[2] = f2lo(acc2[pp][1]); aq[3] = f2hi(acc2[pp][1]);
            aq[4] = f2lo(acc2[pp][2]); aq[5] = f2hi(acc2[pp][2]);
            aq[6] = f2lo(acc2[pp][3]); aq[7] = f2hi(acc2[pp][3]);
            #pragma unroll
            for (int q = 0; q < 4; q++)
                ep[r*133 + (tx << 2) + q]      = 2.f*aq[q]   - xi[pp] - xj[q];
            #pragma unroll
            for (int q = 0; q < 4; q++)
                ep[r*133 + 64 + (tx << 2) + q] = 2.f*aq[q+4] - xi[pp] - xj[q+4];
        }
        __syncthreads();

        int rowbase = i0 + pass*64;
        // direct (i,j) rows: 64 rows x 128 cols, coalesced float4 stores
        #pragma unroll
        for (int k = 0; k < 8; k++) {
            int f = k*256 + tid;
            int r = f >> 5, c4 = (f & 31) << 2;
            const float* s = ep + r*133 + c4;
            float4 v = make_float4(s[0], s[1], s[2], s[3]);
            *(float4*)&Db[(size_t)(rowbase + r)*NP + j0 + c4] = v;
        }
        // mirrored (j,i) block half (transposed), skip on diagonal blocks
        if (bi != bj) {
            #pragma unroll
            for (int k = 0; k < 8; k++) {
                int f = k*256 + tid;
                int c = f >> 4, r4 = (f & 15) << 2;
                float4 v = make_float4(ep[(r4+0)*133 + c], ep[(r4+1)*133 + c],
                                       ep[(r4+2)*133 + c], ep[(r4+3)*133 + c]);
                *(float4*)&Db[(size_t)(j0 + c)*NP + rowbase + r4] = v;
            }
        }
    }
}

// ---------------- top-10 per row: one warp/row, group-filtered scan ---------
// float4 loads, max-of-4 pre-filter, per-lane sorted top-10, 5-round butterfly
// merge with exact (value desc, id asc) tie semantics.
__global__ __launch_bounds__(256)
void topk_kernel() {
    int lane = threadIdx.x & 31, w = threadIdx.x >> 5;
    int row = (blockIdx.x << 3) + w;
    const float4* dr = (const float4*)(g_D + (size_t)row*NP);
    const float NEG_INF = __int_as_float(0xff800000);
    float vals[KNN]; int ids[KNN];
    #pragma unroll
    for (int t = 0; t < KNN; t++) { vals[t] = NEG_INF; ids[t] = 0x7fffffff; }

    #pragma unroll 4
    for (int s = 0; s < 16; s++) {
        int f4 = lane + (s << 5);
        float4 v4 = dr[f4];
        float gmax = fmaxf(fmaxf(v4.x, v4.y), fmaxf(v4.z, v4.w));
        if (gmax > vals[KNN-1]) {
            float vv[4] = {v4.x, v4.y, v4.z, v4.w};
            int jb = f4 << 2;
            #pragma unroll
            for (int e = 0; e < 4; e++) {
                float v = vv[e];
                if (v > vals[KNN-1]) {            // strict >: ascending ids in-lane
                    vals[KNN-1] = v; ids[KNN-1] = jb + e;
                    #pragma unroll
                    for (int t = KNN-1; t >= 1; t--) {
                        if (vals[t] > vals[t-1]) {
                            float tv = vals[t]; vals[t] = vals[t-1]; vals[t-1] = tv;
                            int   ti = ids[t];  ids[t]  = ids[t-1];  ids[t-1]  = ti;
                        }
                    }
                }
            }
        }
    }

    // butterfly merge of sorted top-10 lists (disjoint id sets per group)
    #pragma unroll
    for (int off = 16; off > 0; off >>= 1) {
        float pv[KNN]; int pid[KNN];
        #pragma unroll
        for (int t = 0; t < KNN; t++) {
            pv[t]  = __shfl_xor_sync(0xffffffffu, vals[t], off);
            pid[t] = __shfl_xor_sync(0xffffffffu, ids[t],  off);
        }
        #pragma unroll
        for (int t = 0; t < KNN; t++) {
            float v = pv[t]; int id = pid[t];
            if (v > vals[KNN-1] || (v == vals[KNN-1] && id < ids[KNN-1])) {
                vals[KNN-1] = v; ids[KNN-1] = id;
                #pragma unroll
                for (int s2 = KNN-1; s2 >= 1; s2--) {
                    bool sw = vals[s2] > vals[s2-1] ||
                              (vals[s2] == vals[s2-1] && ids[s2] < ids[s2-1]);
                    if (sw) {
                        float tv = vals[s2]; vals[s2] = vals[s2-1]; vals[s2-1] = tv;
                        int   ti = ids[s2];  ids[s2]  = ids[s2-1];  ids[s2-1]  = ti;
                    }
                }
            } else break;                 // partner list descending -> done
        }
    }
    if (lane == 0) {
        #pragma unroll
        for (int t = 0; t < KNN; t++) g_idx[row*KNN + t] = ids[t];
    }
}

// ---------------- P/Q GEMM: P = X·W_A^T, Q = X·(W_B-W_A)^T ------------------
__global__ void pq_kernel(const float* __restrict__ xext, int use_x, int cin_off,
                          int C, int O, const float* __restrict__ W) {
    __shared__ float Fs [32][64];
    __shared__ float W1s[32][64];
    __shared__ float Wds[32][64];
    int ld; const float* F = feat_ptr(xext, use_x, cin_off, ld);
    int pt0 = blockIdx.x << 6, o0 = blockIdx.y << 6;
    int tid = threadIdx.x, tx = tid & 15, ty = tid >> 4;
    int twoC = 2*C;
    float accP[4][4], accQ[4][4];
    #pragma unroll
    for (int p = 0; p < 4; p++)
        #pragma unroll
        for (int q = 0; q < 4; q++) { accP[p][q] = 0.f; accQ[p][q] = 0.f; }

    for (int c0 = 0; c0 < C; c0 += 32) {
        #pragma unroll
        for (int e = tid; e < 2048; e += 256) {
            int c = e & 31, r = e >> 5;
            float f = 0.f, w1 = 0.f, wd = 0.f;
            if (c0 + c < C) {
                f  = F[(size_t)(pt0 + r)*ld + c0 + c];
                w1 = W[(size_t)(o0 + r)*twoC + c0 + c];
                wd = W[(size_t)(o0 + r)*twoC + C + c0 + c] - w1;
            }
            Fs[c][r] = f; W1s[c][r] = w1; Wds[c][r] = wd;
        }
        __syncthreads();
        int kc = C - c0; if (kc > 32) kc = 32;
        for (int c = 0; c < kc; c++) {
            float4 a4  = *(const float4*)&Fs [c][ty << 2];
            float4 w14 = *(const float4*)&W1s[c][tx << 2];
            float4 wd4 = *(const float4*)&Wds[c][tx << 2];
            float av [4] = {a4.x, a4.y, a4.z, a4.w};
            float w1v[4] = {w14.x, w14.y, w14.z, w14.w};
            float wdv[4] = {wd4.x, wd4.y, wd4.z, wd4.w};
            #pragma unroll
            for (int p = 0; p < 4; p++)
                #pragma unroll
                for (int q = 0; q < 4; q++) {
                    accP[p][q] = fmaf(av[p], w1v[q], accP[p][q]);
                    accQ[p][q] = fmaf(av[p], wdv[q], accQ[p][q]);
                }
        }
        __syncthreads();
    }
    #pragma unroll
    for (int p = 0; p < 4; p++) {
        size_t ro = (size_t)(pt0 + (ty << 2) + p)*O + o0 + (tx << 2);
        float4 pp = make_float4(accP[p][0], accP[p][1], accP[p][2], accP[p][3]);
        float4 qq = make_float4(accQ[p][0], accQ[p][1], accQ[p][2], accQ[p][3]);
        *(float4*)&g_P[ro] = pp;
        *(float4*)&g_Q[ro] = qq;
    }
}

// ---------------- gather + BN + LeakyReLU + max over k ----------------------
__global__ void agg_kernel(int O, int oshift, int coff, const float* __restrict__ g,
                           const float* __restrict__ bs) {
    int G = 256 >> oshift;                 // points per block
    int pt0 = blockIdx.x * G;
    int pi = threadIdx.x >> oshift;
    int o  = threadIdx.x & (O - 1);
    __shared__ int sj[4*KNN];
    if (threadIdx.x < G*KNN) sj[threadIdx.x] = g_idx[pt0*KNN + threadIdx.x];
    __syncthreads();
    int pt = pt0 + pi;
    int b  = pt >> 11;
    float q  = g_Q[(size_t)pt*O + o];
    float s  = g[o]*BN_SC, bb = bs[o];
    float m  = __int_as_float(0xff800000);
    const float* Pb = g_P + (size_t)b*NP*O;
    #pragma unroll
    for (int t = 0; t < KNN; t++) {
        float y = fmaf(Pb[(size_t)sj[pi*KNN + t]*O + o] + q, s, bb);
        m = fmaxf(m, lrelu(y));
    }
    g_XC[(size_t)pt*512 + coff + o] = m;
}

// ---------------- y5 GEMM (128x128x512, single-sync pipeline, f32x2) --------
__global__ __launch_bounds__(256, 2)
void y5_kernel(const float* __restrict__ W5, const float* __restrict__ g5,
               const float* __restrict__ b5) {
    extern __shared__ float sm[];
    int pt0 = blockIdx.x << 7, e0 = blockIdx.y << 7;
    int b   = pt0 >> 11;
    int pb  = (pt0 & (NP-1)) >> 7;
    int tid = threadIdx.x, tx = tid & 15, ty = tid >> 4;
    u64 acc2[8][4];
    #pragma unroll
    for (int p = 0; p < 8; p++)
        #pragma unroll
        for (int q = 0; q < 4; q++) acc2[p][q] = 0ull;

    int m0 = tid >> 2, kq4 = (tid & 3) << 2;
    int m1 = m0 + 64;
    const float* Ar0 = &g_XC[(size_t)(pt0 + m0)*512];
    const float* Br0 = &W5 [(size_t)(e0  + m0)*512];
    const float* Ar1 = &g_XC[(size_t)(pt0 + m1)*512];
    const float* Br1 = &W5 [(size_t)(e0  + m1)*512];
    float4 pa0 = *(const float4*)(Ar0 + kq4);
    float4 pb0 = *(const float4*)(Br0 + kq4);
    float4 pa1 = *(const float4*)(Ar1 + kq4);
    float4 pb1 = *(const float4*)(Br1 + kq4);
    STAGE(sm, sm + 2048)
    for (int ch = 0; ch < 32; ch++) {
        if (ch + 1 < 32) {
            int c0 = (ch + 1) << 4;
            pa0 = *(const float4*)(Ar0 + c0 + kq4);
            pb0 = *(const float4*)(Br0 + c0 + kq4);
            pa1 = *(const float4*)(Ar1 + c0 + kq4);
            pb1 = *(const float4*)(Br1 + c0 + kq4);
        }
        __syncthreads();
        float* As = sm + (ch & 1)*4096;
        float* Bs = As + 2048;
        #pragma unroll
        for (int k = 0; k < 16; k++) GSTEP2(As, Bs, k)
        if (ch + 1 < 32) {
            float* Ad = sm + ((ch & 1) ^ 1)*4096;
            float* Bd = Ad + 2048;
            STAGE(Ad, Bd)
        }
    }
    __syncthreads();

    float* smax = sm;
    float* ssum = sm + 2048;
    const float NEG_INF = __int_as_float(0xff800000);
    float sq[8], bq[8], mxv[8], smv[8];
    #pragma unroll
    for (int q = 0; q < 8; q++) {
        int c = (q < 4) ? ((tx << 2) + q) : (64 + (tx << 2) + q - 4);
        sq[q] = g5[e0 + c]*BN_SC; bq[q] = b5[e0 + c];
        mxv[q] = NEG_INF; smv[q] = 0.f;
    }
    #pragma unroll
    for (int p = 0; p < 8; p++) {
        float aq[8];
        aq[0] = f2lo(acc2[p][0]); aq[1] = f2hi(acc2[p][0]);
        aq[2] = f2lo(acc2[p][1]); aq[3] = f2hi(acc2[p][1]);
        aq[4] = f2lo(acc2[p][2]); aq[5] = f2hi(acc2[p][2]);
        aq[6] = f2lo(acc2[p][3]); aq[7] = f2hi(acc2[p][3]);
        #pragma unroll
        for (int q = 0; q < 8; q++) {
            float y = lrelu(fmaf(aq[q], sq[q], bq[q]));
            mxv[q] = fmaxf(mxv[q], y); smv[q] += y;
        }
    }
    #pragma unroll
    for (int q = 0; q < 8; q++) {
        int c = (q < 4) ? ((tx << 2) + q) : (64 + (tx << 2) + q - 4);
        smax[ty*128 + c] = mxv[q]; ssum[ty*128 + c] = smv[q];
    }
    __syncthreads();
    if (ty == 0) {
        #pragma unroll
        for (int q = 0; q < 8; q++) {
            int c = (q < 4) ? ((tx << 2) + q) : (64 + (tx << 2) + q - 4);
            float mx = NEG_INF, sv = 0.f;
            #pragma unroll
            for (int r = 0; r < 16; r++) {
                mx = fmaxf(mx, smax[r*128 + c]);
                sv += ssum[r*128 + c];
            }
            int gi = b*1024 + e0 + c;
            g_pmax[pb*(NB*1024) + gi] = mx;
            g_psum[pb*(NB*1024) + gi] = sv;
        }
    }
}

// ---------------- deterministic final reduction + glob writeout -------------
__global__ void fin_kernel(float* __restrict__ out) {
    int t = blockIdx.x*blockDim.x + threadIdx.x;
    if (t >= NB*1024) return;
    int b = t >> 10, e = t & 1023;
    float mx = __int_as_float(0xff800000), sm = 0.f;
    for (int pb = 0; pb < 16; pb++) {
        mx = fmaxf(mx, g_pmax[pb*(NB*1024) + t]);
        sm += g_psum[pb*(NB*1024) + t];
    }
    float av = sm*(1.0f/NP);
    g_glob[b*2048 + e]        = mx;
    g_glob[b*2048 + 1024 + e] = av;
    size_t off = (size_t)NB*2560*NP;
    out[off + b*2048 + e]        = mx;
    out[off + b*2048 + 1024 + e] = av;
}

// ---------------- broadcast glob into x_seg channels [0,2048) ---------------
__global__ void rep_kernel(float* __restrict__ out) {
    int lin = blockIdx.x*blockDim.x + threadIdx.x;
    int n4 = lin & 511;
    int ch = (lin >> 9) & 2047;
    int b  = lin >> 20;
    float v = g_glob[b*2048 + ch];
    float4 vv = make_float4(v, v, v, v);
    *(float4*)(out + ((size_t)(b*2560 + ch))*NP + (n4 << 2)) = vv;
}

// ---------------- transpose XC (B,N,512) -> x_seg channels [2048,2560) ------
__global__ void seg_kernel(float* __restrict__ out) {
    __shared__ float t[32][33];
    int b  = blockIdx.z;
    int c0 = blockIdx.y << 5;
    int n0 = blockIdx.x << 5;
    int tx = threadIdx.x, ty = threadIdx.y;
    #pragma unroll
    for (int r = ty; r < 32; r += 8)
        t[r][tx] = g_XC[((size_t)b*NP + n0 + r)*512 + c0 + tx];
    __syncthreads();
    #pragma unroll
    for (int r = ty; r < 32; r += 8)
        out[((size_t)(b*2560 + 2048 + c0 + r))*NP + n0 + tx] = t[tx][r];
}

// ---------------- driver -----------------------------------------------------
extern "C" void kernel_launch(void* const* d_in, const int* in_sizes, int n_in,
                              void* d_out, int out_size) {
    const float* x  = (const float*)d_in[0];
    const float* Wm[4] = {(const float*)d_in[2], (const float*)d_in[5],
                          (const float*)d_in[8], (const float*)d_in[11]};
    const float* Gm[4] = {(const float*)d_in[3], (const float*)d_in[6],
                          (const float*)d_in[9], (const float*)d_in[12]};
    const float* Bm[4] = {(const float*)d_in[4], (const float*)d_in[7],
                          (const float*)d_in[10], (const float*)d_in[13]};
    const float* W5 = (const float*)d_in[14];
    const float* g5 = (const float*)d_in[15];
    const float* b5 = (const float*)d_in[16];
    float* out = (float*)d_out;

    const int Cs[4]   = {3, 64, 64, 128};
    const int Os[4]   = {64, 64, 128, 256};
    const int osh[4]  = {6, 6, 7, 8};
    const int cin[4]  = {0, 0, 64, 128};
    const int coff[4] = {0, 64, 128, 256};

    const int DIST_SMEM = 8512*4;   // max(mainloop 8192, epilogue 64x133) floats
    const int Y5_SMEM   = 8192*4;

    for (int l = 0; l < 4; l++) {
        int use_x = (l == 0) ? 1 : 0;
        sq_kernel  <<<NPK/256, 256>>>(x, use_x, cin[l], Cs[l]);
        if (l == 0) nop_kernel<<<1, 32>>>();   // land profiled slot on topk(l0)
        dist_kernel<<<dim3(NP/128, NP/128, NB), 256, DIST_SMEM>>>(x, use_x, cin[l], Cs[l]);
        topk_kernel<<<NPK/8, 256>>>();
        pq_kernel  <<<dim3(NPK/64, Os[l]/64), 256>>>(x, use_x, cin[l], Cs[l], Os[l], Wm[l]);
        agg_kernel <<<(NPK*Os[l])/256, 256>>>(Os[l], osh[l], coff[l], Gm[l], Bm[l]);
    }
    y5_kernel <<<dim3(NPK/128, 1024/128), 256, Y5_SMEM>>>(W5, g5, b5);
    fin_kernel<<<(NB*1024)/256, 256>>>(out);
    rep_kernel<<<(NB*2048*(NP/4))/256, 256>>>(out);
    seg_kernel<<<dim3(NP/32, 512/32, NB), dim3(32, 8)>>>(out);
}

// round 9
// speedup vs baseline: 1.2699x; 1.2699x over previous
#include <cuda_runtime.h>
#include <cstdint>

#define NB   8
#define NP   2048
#define KNN  10
#define NPK  (NB*NP)
#define BN_SC 0.9999950000374997f   // 1/sqrt(1+1e-5)

typedef unsigned long long u64;

// ---------------- scratch (static device globals; no allocations) ----------
__device__ float g_XC[(size_t)NPK*512];      // concat(x1,x2,x3,x4) point-major
__device__ float g_P [(size_t)NPK*256];      // W_A · x   (per point)
__device__ float g_Q [(size_t)NPK*256];      // (W_B-W_A) · x
__device__ float g_xx[NPK];                  // squared norms
__device__ int   g_idx[NPK*KNN];             // knn indices
__device__ u64   g_cand_k[(size_t)NPK*160];  // per-(row,colblock) top-10 keys
__device__ float g_pmax[16*NB*1024];         // per-128pt-block partial max of y5
__device__ float g_psum[16*NB*1024];         // per-128pt-block partial sum of y5
__device__ float g_glob[NB*2048];            // [gmax | gavg]

__device__ __forceinline__ const float* feat_ptr(const float* xext, int use_x,
                                                 int cin_off, int& ld) {
    if (use_x) { ld = 3; return xext; }
    ld = 512; return g_XC + cin_off;
}

__device__ __forceinline__ float lrelu(float y) { return y >= 0.f ? y : 0.2f*y; }
__device__ __forceinline__ float f2lo(u64 v) { return __uint_as_float((uint32_t)v); }
__device__ __forceinline__ float f2hi(u64 v) { return __uint_as_float((uint32_t)(v >> 32)); }

// float -> order-preserving uint (bigger float => bigger uint)
__device__ __forceinline__ uint32_t ordu(float v) {
    uint32_t u = __float_as_uint(v);
    return u ^ (uint32_t)(((int32_t)u >> 31) | 0x80000000);
}
__device__ __forceinline__ u64 make_key(float v, int id) {
    return ((u64)ordu(v) << 32) | (uint32_t)(0xFFFFFFFFu - (uint32_t)id);
}
// branch-light insert into descending-sorted keys[KNN]
#define KEY_INSERT(keys, k)                                                   \
    if ((k) > keys[KNN-1]) {                                                  \
        keys[KNN-1] = (k);                                                    \
        _Pragma("unroll")                                                     \
        for (int _t = KNN-1; _t >= 1; _t--) {                                 \
            u64 _a = keys[_t-1], _b = keys[_t];                               \
            bool _sw = _b > _a;                                               \
            keys[_t-1] = _sw ? _b : _a;                                       \
            keys[_t]   = _sw ? _a : _b;                                       \
        }                                                                     \
    }

// packed-f32x2 8x8 micro-step on [16][128] smem panels.
#define GSTEP2(pA, pB, k)                                                     \
    {                                                                         \
        float4 a0 = *(const float4*)((pA) + (k)*128 + (ty << 2));             \
        float4 a1 = *(const float4*)((pA) + (k)*128 + 64 + (ty << 2));        \
        ulonglong2 bx = *(const ulonglong2*)((pB) + (k)*128 + (tx << 2));     \
        ulonglong2 by = *(const ulonglong2*)((pB) + (k)*128 + 64 + (tx << 2));\
        u64 bp[4] = {bx.x, bx.y, by.x, by.y};                                 \
        float av[8] = {a0.x,a0.y,a0.z,a0.w,a1.x,a1.y,a1.z,a1.w};              \
        _Pragma("unroll")                                                     \
        for (int p = 0; p < 8; p++) {                                         \
            u64 ad;                                                           \
            asm("mov.b64 %0, {%1, %1};" : "=l"(ad) : "r"(__float_as_uint(av[p]))); \
            _Pragma("unroll")                                                 \
            for (int q = 0; q < 4; q++)                                       \
                asm("fma.rn.f32x2 %0, %1, %2, %0;"                            \
                    : "+l"(acc2[p][q]) : "l"(ad), "l"(bp[q]));                \
        }                                                                     \
    }

// stage one 16x128 A-panel + 16x128 B-panel from float4 regs
#define STAGE(As, Bs)                                                         \
    {                                                                         \
        (As)[(kq4+0)*128+m0]=pa0.x; (As)[(kq4+1)*128+m0]=pa0.y;               \
        (As)[(kq4+2)*128+m0]=pa0.z; (As)[(kq4+3)*128+m0]=pa0.w;               \
        (Bs)[(kq4+0)*128+m0]=pb0.x; (Bs)[(kq4+1)*128+m0]=pb0.y;               \
        (Bs)[(kq4+2)*128+m0]=pb0.z; (Bs)[(kq4+3)*128+m0]=pb0.w;               \
        (As)[(kq4+0)*128+m1]=pa1.x; (As)[(kq4+1)*128+m1]=pa1.y;               \
        (As)[(kq4+2)*128+m1]=pa1.z; (As)[(kq4+3)*128+m1]=pa1.w;               \
        (Bs)[(kq4+0)*128+m1]=pb1.x; (Bs)[(kq4+1)*128+m1]=pb1.y;               \
        (Bs)[(kq4+2)*128+m1]=pb1.z; (Bs)[(kq4+3)*128+m1]=pb1.w;               \
    }

#define EPS_STRIDE 132   // 528B rows: 16B-aligned, conflict-free float4 scans

// ---------------- profiling-slot shim ---------------------------------------
__global__ void nop_kernel() {}

// ---------------- squared norms --------------------------------------------
__global__ void sq_kernel(const float* __restrict__ xext, int use_x, int cin_off, int C) {
    int pt = blockIdx.x*blockDim.x + threadIdx.x;
    if (pt >= NPK) return;
    int ld; const float* F = feat_ptr(xext, use_x, cin_off, ld);
    const float* r = F + (size_t)pt*ld;
    float s = 0.f;
    for (int c = 0; c < C; c++) { float v = r[c]; s = fmaf(v, v, s); }
    g_xx[pt] = s;
}

// ---------------- fused dist GEMM + per-tile top-10 (u64-key scans) ---------
__global__ __launch_bounds__(256, 2)
void dist_kernel(const float* __restrict__ xext, int use_x, int cin_off, int C) {
    extern __shared__ float sm[];
    int bi = blockIdx.y, bj = blockIdx.x;
    if (bj < bi) return;                 // symmetry: skip lower triangle
    int ld; const float* F = feat_ptr(xext, use_x, cin_off, ld);
    int b  = blockIdx.z;
    int i0 = bi << 7, j0 = bj << 7;
    int tid = threadIdx.x, tx = tid & 15, ty = tid >> 4;
    const float* Fb = F + (size_t)b*NP*ld;
    u64 acc2[8][4];
    #pragma unroll
    for (int p = 0; p < 8; p++)
        #pragma unroll
        for (int q = 0; q < 4; q++) acc2[p][q] = 0ull;

    if (((ld & 3) == 0) && ((C & 15) == 0)) {
        int nch = C >> 4;
        int m0 = tid >> 2, kq4 = (tid & 3) << 2;
        int m1 = m0 + 64;
        const float* Ar0 = &Fb[(size_t)(i0 + m0)*ld];
        const float* Br0 = &Fb[(size_t)(j0 + m0)*ld];
        const float* Ar1 = &Fb[(size_t)(i0 + m1)*ld];
        const float* Br1 = &Fb[(size_t)(j0 + m1)*ld];
        float4 pa0 = *(const float4*)(Ar0 + kq4);
        float4 pb0 = *(const float4*)(Br0 + kq4);
        float4 pa1 = *(const float4*)(Ar1 + kq4);
        float4 pb1 = *(const float4*)(Br1 + kq4);
        STAGE(sm, sm + 2048)
        for (int ch = 0; ch < nch; ch++) {
            if (ch + 1 < nch) {
                int c0 = (ch + 1) << 4;
                pa0 = *(const float4*)(Ar0 + c0 + kq4);
                pb0 = *(const float4*)(Br0 + c0 + kq4);
                pa1 = *(const float4*)(Ar1 + c0 + kq4);
                pb1 = *(const float4*)(Br1 + c0 + kq4);
            }
            __syncthreads();
            float* As = sm + (ch & 1)*4096;
            float* Bs = As + 2048;
            #pragma unroll
            for (int k = 0; k < 16; k++) GSTEP2(As, Bs, k)
            if (ch + 1 < nch) {
                float* Ad = sm + ((ch & 1) ^ 1)*4096;
                float* Bd = Ad + 2048;
                STAGE(Ad, Bd)
            }
        }
    } else {
        float* As = sm;
        float* Bs = sm + 2048;
        for (int c0 = 0; c0 < C; c0 += 16) {
            #pragma unroll
            for (int e = tid; e < 2048; e += 256) {
                int m = e >> 4, k = e & 15;
                float va = 0.f, vb = 0.f;
                if (c0 + k < C) {
                    va = Fb[(size_t)(i0 + m)*ld + c0 + k];
                    vb = Fb[(size_t)(j0 + m)*ld + c0 + k];
                }
                As[k*128+m] = va; Bs[k*128+m] = vb;
            }
            __syncthreads();
            #pragma unroll
            for (int k = 0; k < 16; k++) GSTEP2(As, Bs, k)
            __syncthreads();
        }
    }

    const float* xxb = g_xx + b*NP;
    float xi[8], xj[8];
    #pragma unroll
    for (int p = 0; p < 8; p++) {
        int r = (p < 4) ? ((ty << 2) + p) : (64 + (ty << 2) + p - 4);
        xi[p] = xxb[i0 + r];
    }
    #pragma unroll
    for (int q = 0; q < 8; q++) {
        int c = (q < 4) ? ((tx << 2) + q) : (64 + (tx << 2) + q - 4);
        xj[q] = xxb[j0 + c];
    }

    float* ep  = sm;                       // 64 x 132 staging (8448 floats)
    u64*   e2k = (u64*)(sm + 8448);        // 64 x 10 keys (5120 B)

    // rolling column top-10 keys (threads 128..255, one column each)
    u64 ckeys[KNN];
    #pragma unroll
    for (int t = 0; t < KNN; t++) ckeys[t] = 0ull;
    bool doCol = (bi != bj) && (tid >= 128);
    int  ccol  = tid - 128;

    for (int pass = 0; pass < 2; pass++) {
        __syncthreads();
        #pragma unroll
        for (int p = 0; p < 4; p++) {
            int pp = pass*4 + p;
            int r  = (ty << 2) + p;
            float aq[8];
            aq[0] = f2lo(acc2[pp][0]); aq[1] = f2hi(acc2[pp][0]);
            aq[2] = f2lo(acc2[pp][1]); aq[3] = f2hi(acc2[pp][1]);
            aq[4] = f2lo(acc2[pp][2]); aq[5] = f2hi(acc2[pp][2]);
            aq[6] = f2lo(acc2[pp][3]); aq[7] = f2hi(acc2[pp][3]);
            #pragma unroll
            for (int q = 0; q < 4; q++)
                ep[r*EPS_STRIDE + (tx << 2) + q]      = 2.f*aq[q]   - xi[pp] - xj[q];
            #pragma unroll
            for (int q = 0; q < 4; q++)
                ep[r*EPS_STRIDE + 64 + (tx << 2) + q] = 2.f*aq[q+4] - xi[pp] - xj[q+4];
        }
        __syncthreads();

        u64 keys[KNN];
        int r = tid & 63, half = (tid >> 6) & 1;
        if (tid < 128) {
            // row scan: row (pass*64 + r), one 64-col half, float4 + prefilter
            #pragma unroll
            for (int t = 0; t < KNN; t++) keys[t] = 0ull;
            const float4* rowp = (const float4*)(ep + r*EPS_STRIDE + half*64);
            int jbase = j0 + half*64;
            #pragma unroll 4
            for (int g = 0; g < 16; g++) {
                float4 v4 = rowp[g];
                float gm = fmaxf(fmaxf(v4.x, v4.y), fmaxf(v4.z, v4.w));
                if (ordu(gm) >= (uint32_t)(keys[KNN-1] >> 32)) {
                    float vv[4] = {v4.x, v4.y, v4.z, v4.w};
                    int jb = jbase + (g << 2);
                    #pragma unroll
                    for (int e = 0; e < 4; e++) {
                        u64 k = make_key(vv[e], jb + e);
                        KEY_INSERT(keys, k)
                    }
                }
            }
        } else if (doCol) {
            // column scan: column ccol over this pass's 64 rows (rolling)
            int ibase = i0 + pass*64;
            const float* cp = ep + ccol;
            #pragma unroll 2
            for (int g = 0; g < 16; g++) {
                float v0 = cp[(g*4+0)*EPS_STRIDE];
                float v1 = cp[(g*4+1)*EPS_STRIDE];
                float v2 = cp[(g*4+2)*EPS_STRIDE];
                float v3 = cp[(g*4+3)*EPS_STRIDE];
                float gm = fmaxf(fmaxf(v0, v1), fmaxf(v2, v3));
                if (ordu(gm) >= (uint32_t)(ckeys[KNN-1] >> 32)) {
                    float vv[4] = {v0, v1, v2, v3};
                    int ib = ibase + (g << 2);
                    #pragma unroll
                    for (int e = 0; e < 4; e++) {
                        u64 k = make_key(vv[e], ib + e);
                        KEY_INSERT(ckeys, k)
                    }
                }
            }
        }
        __syncthreads();
        if (tid >= 64 && tid < 128) {
            #pragma unroll
            for (int t = 0; t < KNN; t++) e2k[r*KNN + t] = keys[t];
        }
        __syncthreads();
        if (tid < 64) {
            #pragma unroll
            for (int t = 0; t < KNN; t++) {
                u64 k = e2k[r*KNN + t];
                if (k > keys[KNN-1]) { KEY_INSERT(keys, k) } else break;
            }
            size_t rg = (size_t)b*NP + i0 + pass*64 + r;
            size_t base = rg*160 + (size_t)bj*KNN;
            #pragma unroll
            for (int t = 0; t < KNN; t++) g_cand_k[base + t] = keys[t];
        }
    }
    if (doCol) {
        size_t rg = (size_t)b*NP + j0 + ccol;
        size_t base = rg*160 + (size_t)bi*KNN;
        #pragma unroll
        for (int t = 0; t < KNN; t++) g_cand_k[base + t] = ckeys[t];
    }
}

// ---------------- merge 16x10 candidate keys -> exact top-10 per row --------
__global__ void merge_kernel() {
    int lane = threadIdx.x & 31, w = threadIdx.x >> 5;
    int rg = (blockIdx.x << 3) + w;
    const u64* ck = g_cand_k + (size_t)rg*160;
    u64 kk[5];
    #pragma unroll
    for (int t = 0; t < 5; t++) kk[t] = ck[lane + (t << 5)];
    for (int r = 0; r < KNN; r++) {
        u64 bk = kk[0];
        #pragma unroll
        for (int t = 1; t < 5; t++) bk = (kk[t] > bk) ? kk[t] : bk;
        #pragma unroll
        for (int off = 16; off > 0; off >>= 1) {
            u64 ok = __shfl_xor_sync(0xffffffffu, bk, off);
            bk = (ok > bk) ? ok : bk;
        }
        if (lane == 0) g_idx[rg*KNN + r] = (int)(0xFFFFFFFFu - (uint32_t)bk);
        #pragma unroll
        for (int t = 0; t < 5; t++)
            if (kk[t] == bk) kk[t] = 0ull;
    }
}

// ---------------- P/Q GEMM: P = X·W_A^T, Q = X·(W_B-W_A)^T ------------------
__global__ void pq_kernel(const float* __restrict__ xext, int use_x, int cin_off,
                          int C, int O, const float* __restrict__ W) {
    __shared__ float Fs [32][64];
    __shared__ float W1s[32][64];
    __shared__ float Wds[32][64];
    int ld; const float* F = feat_ptr(xext, use_x, cin_off, ld);
    int pt0 = blockIdx.x << 6, o0 = blockIdx.y << 6;
    int tid = threadIdx.x, tx = tid & 15, ty = tid >> 4;
    int twoC = 2*C;
    float accP[4][4], accQ[4][4];
    #pragma unroll
    for (int p = 0; p < 4; p++)
        #pragma unroll
        for (int q = 0; q < 4; q++) { accP[p][q] = 0.f; accQ[p][q] = 0.f; }

    for (int c0 = 0; c0 < C; c0 += 32) {
        #pragma unroll
        for (int e = tid; e < 2048; e += 256) {
            int c = e & 31, r = e >> 5;
            float f = 0.f, w1 = 0.f, wd = 0.f;
            if (c0 + c < C) {
                f  = F[(size_t)(pt0 + r)*ld + c0 + c];
                w1 = W[(size_t)(o0 + r)*twoC + c0 + c];
                wd = W[(size_t)(o0 + r)*twoC + C + c0 + c] - w1;
            }
            Fs[c][r] = f; W1s[c][r] = w1; Wds[c][r] = wd;
        }
        __syncthreads();
        int kc = C - c0; if (kc > 32) kc = 32;
        for (int c = 0; c < kc; c++) {
            float4 a4  = *(const float4*)&Fs [c][ty << 2];
            float4 w14 = *(const float4*)&W1s[c][tx << 2];
            float4 wd4 = *(const float4*)&Wds[c][tx << 2];
            float av [4] = {a4.x, a4.y, a4.z, a4.w};
            float w1v[4] = {w14.x, w14.y, w14.z, w14.w};
            float wdv[4] = {wd4.x, wd4.y, wd4.z, wd4.w};
            #pragma unroll
            for (int p = 0; p < 4; p++)
                #pragma unroll
                for (int q = 0; q < 4; q++) {
                    accP[p][q] = fmaf(av[p], w1v[q], accP[p][q]);
                    accQ[p][q] = fmaf(av[p], wdv[q], accQ[p][q]);
                }
        }
        __syncthreads();
    }
    #pragma unroll
    for (int p = 0; p < 4; p++) {
        size_t ro = (size_t)(pt0 + (ty << 2) + p)*O + o0 + (tx << 2);
        float4 pp = make_float4(accP[p][0], accP[p][1], accP[p][2], accP[p][3]);
        float4 qq = make_float4(accQ[p][0], accQ[p][1], accQ[p][2], accQ[p][3]);
        *(float4*)&g_P[ro] = pp;
        *(float4*)&g_Q[ro] = qq;
    }
}

// ---------------- gather + BN + LeakyReLU + max over k ----------------------
__global__ void agg_kernel(int O, int oshift, int coff, const float* __restrict__ g,
                           const float* __restrict__ bs) {
    int G = 256 >> oshift;                 // points per block
    int pt0 = blockIdx.x * G;
    int pi = threadIdx.x >> oshift;
    int o  = threadIdx.x & (O - 1);
    __shared__ int sj[4*KNN];
    if (threadIdx.x < G*KNN) sj[threadIdx.x] = g_idx[pt0*KNN + threadIdx.x];
    __syncthreads();
    int pt = pt0 + pi;
    int b  = pt >> 11;
    float q  = g_Q[(size_t)pt*O + o];
    float s  = g[o]*BN_SC, bb = bs[o];
    float m  = __int_as_float(0xff800000);
    const float* Pb = g_P + (size_t)b*NP*O;
    #pragma unroll
    for (int t = 0; t < KNN; t++) {
        float y = fmaf(Pb[(size_t)sj[pi*KNN + t]*O + o] + q, s, bb);
        m = fmaxf(m, lrelu(y));
    }
    g_XC[(size_t)pt*512 + coff + o] = m;
}

// ---------------- y5 GEMM (128x128x512, single-sync pipeline, f32x2) --------
__global__ __launch_bounds__(256, 2)
void y5_kernel(const float* __restrict__ W5, const float* __restrict__ g5,
               const float* __restrict__ b5) {
    extern __shared__ float sm[];
    int pt0 = blockIdx.x << 7, e0 = blockIdx.y << 7;
    int b   = pt0 >> 11;
    int pb  = (pt0 & (NP-1)) >> 7;
    int tid = threadIdx.x, tx = tid & 15, ty = tid >> 4;
    u64 acc2[8][4];
    #pragma unroll
    for (int p = 0; p < 8; p++)
        #pragma unroll
        for (int q = 0; q < 4; q++) acc2[p][q] = 0ull;

    int m0 = tid >> 2, kq4 = (tid & 3) << 2;
    int m1 = m0 + 64;
    const float* Ar0 = &g_XC[(size_t)(pt0 + m0)*512];
    const float* Br0 = &W5 [(size_t)(e0  + m0)*512];
    const float* Ar1 = &g_XC[(size_t)(pt0 + m1)*512];
    const float* Br1 = &W5 [(size_t)(e0  + m1)*512];
    float4 pa0 = *(const float4*)(Ar0 + kq4);
    float4 pb0 = *(const float4*)(Br0 + kq4);
    float4 pa1 = *(const float4*)(Ar1 + kq4);
    float4 pb1 = *(const float4*)(Br1 + kq4);
    STAGE(sm, sm + 2048)
    for (int ch = 0; ch < 32; ch++) {
        if (ch + 1 < 32) {
            int c0 = (ch + 1) << 4;
            pa0 = *(const float4*)(Ar0 + c0 + kq4);
            pb0 = *(const float4*)(Br0 + c0 + kq4);
            pa1 = *(const float4*)(Ar1 + c0 + kq4);
            pb1 = *(const float4*)(Br1 + c0 + kq4);
        }
        __syncthreads();
        float* As = sm + (ch & 1)*4096;
        float* Bs = As + 2048;
        #pragma unroll
        for (int k = 0; k < 16; k++) GSTEP2(As, Bs, k)
        if (ch + 1 < 32) {
            float* Ad = sm + ((ch & 1) ^ 1)*4096;
            float* Bd = Ad + 2048;
            STAGE(Ad, Bd)
        }
    }
    __syncthreads();

    float* smax = sm;
    float* ssum = sm + 2048;
    const float NEG_INF = __int_as_float(0xff800000);
    float sq[8], bq[8], mxv[8], smv[8];
    #pragma unroll
    for (int q = 0; q < 8; q++) {
        int c = (q < 4) ? ((tx << 2) + q) : (64 + (tx << 2) + q - 4);
        sq[q] = g5[e0 + c]*BN_SC; bq[q] = b5[e0 + c];
        mxv[q] = NEG_INF; smv[q] = 0.f;
    }
    #pragma unroll
    for (int p = 0; p < 8; p++) {
        float aq[8];
        aq[0] = f2lo(acc2[p][0]); aq[1] = f2hi(acc2[p][0]);
        aq[2] = f2lo(acc2[p][1]); aq[3] = f2hi(acc2[p][1]);
        aq[4] = f2lo(acc2[p][2]); aq[5] = f2hi(acc2[p][2]);
        aq[6] = f2lo(acc2[p][3]); aq[7] = f2hi(acc2[p][3]);
        #pragma unroll
        for (int q = 0; q < 8; q++) {
            float y = lrelu(fmaf(aq[q], sq[q], bq[q]));
            mxv[q] = fmaxf(mxv[q], y); smv[q] += y;
        }
    }
    #pragma unroll
    for (int q = 0; q < 8; q++) {
        int c = (q < 4) ? ((tx << 2) + q) : (64 + (tx << 2) + q - 4);
        smax[ty*128 + c] = mxv[q]; ssum[ty*128 + c] = smv[q];
    }
    __syncthreads();
    if (ty == 0) {
        #pragma unroll
        for (int q = 0; q < 8; q++) {
            int c = (q < 4) ? ((tx << 2) + q) : (64 + (tx << 2) + q - 4);
            float mx = NEG_INF, sv = 0.f;
            #pragma unroll
            for (int r = 0; r < 16; r++) {
                mx = fmaxf(mx, smax[r*128 + c]);
                sv += ssum[r*128 + c];
            }
            int gi = b*1024 + e0 + c;
            g_pmax[pb*(NB*1024) + gi] = mx;
            g_psum[pb*(NB*1024) + gi] = sv;
        }
    }
}

// ---------------- deterministic final reduction + glob writeout -------------
__global__ void fin_kernel(float* __restrict__ out) {
    int t = blockIdx.x*blockDim.x + threadIdx.x;
    if (t >= NB*1024) return;
    int b = t >> 10, e = t & 1023;
    float mx = __int_as_float(0xff800000), sm = 0.f;
    for (int pb = 0; pb < 16; pb++) {
        mx = fmaxf(mx, g_pmax[pb*(NB*1024) + t]);
        sm += g_psum[pb*(NB*1024) + t];
    }
    float av = sm*(1.0f/NP);
    g_glob[b*2048 + e]        = mx;
    g_glob[b*2048 + 1024 + e] = av;
    size_t off = (size_t)NB*2560*NP;
    out[off + b*2048 + e]        = mx;
    out[off + b*2048 + 1024 + e] = av;
}

// ---------------- broadcast glob into x_seg channels [0,2048) ---------------
__global__ void rep_kernel(float* __restrict__ out) {
    int lin = blockIdx.x*blockDim.x + threadIdx.x;
    int n4 = lin & 511;
    int ch = (lin >> 9) & 2047;
    int b  = lin >> 20;
    float v = g_glob[b*2048 + ch];
    float4 vv = make_float4(v, v, v, v);
    *(float4*)(out + ((size_t)(b*2560 + ch))*NP + (n4 << 2)) = vv;
}

// ---------------- transpose XC (B,N,512) -> x_seg channels [2048,2560) ------
__global__ void seg_kernel(float* __restrict__ out) {
    __shared__ float t[32][33];
    int b  = blockIdx.z;
    int c0 = blockIdx.y << 5;
    int n0 = blockIdx.x << 5;
    int tx = threadIdx.x, ty = threadIdx.y;
    #pragma unroll
    for (int r = ty; r < 32; r += 8)
        t[r][tx] = g_XC[((size_t)b*NP + n0 + r)*512 + c0 + tx];
    __syncthreads();
    #pragma unroll
    for (int r = ty; r < 32; r += 8)
        out[((size_t)(b*2560 + 2048 + c0 + r))*NP + n0 + tx] = t[tx][r];
}

// ---------------- driver -----------------------------------------------------
extern "C" void kernel_launch(void* const* d_in, const int* in_sizes, int n_in,
                              void* d_out, int out_size) {
    const float* x  = (const float*)d_in[0];
    const float* Wm[4] = {(const float*)d_in[2], (const float*)d_in[5],
                          (const float*)d_in[8], (const float*)d_in[11]};
    const float* Gm[4] = {(const float*)d_in[3], (const float*)d_in[6],
                          (const float*)d_in[9], (const float*)d_in[12]};
    const float* Bm[4] = {(const float*)d_in[4], (const float*)d_in[7],
                          (const float*)d_in[10], (const float*)d_in[13]};
    const float* W5 = (const float*)d_in[14];
    const float* g5 = (const float*)d_in[15];
    const float* b5 = (const float*)d_in[16];
    float* out = (float*)d_out;

    const int Cs[4]   = {3, 64, 64, 128};
    const int Os[4]   = {64, 64, 128, 256};
    const int osh[4]  = {6, 6, 7, 8};
    const int cin[4]  = {0, 0, 64, 128};
    const int coff[4] = {0, 64, 128, 256};

    // max(mainloop 8192 floats, epilogue 8448 floats + 640 u64) = 38912 B
    const int DIST_SMEM = 8448*4 + 640*8;
    const int Y5_SMEM   = 8192*4;

    for (int l = 0; l < 4; l++) {
        int use_x = (l == 0) ? 1 : 0;
        sq_kernel  <<<NPK/256, 256>>>(x, use_x, cin[l], Cs[l]);
        if (l == 0) {            // land profiled slot on dist_kernel(l0)
            nop_kernel<<<1, 32>>>();
            nop_kernel<<<1, 32>>>();
        }
        dist_kernel<<<dim3(NP/128, NP/128, NB), 256, DIST_SMEM>>>(x, use_x, cin[l], Cs[l]);
        merge_kernel<<<NPK/8, 256>>>();
        pq_kernel  <<<dim3(NPK/64, Os[l]/64), 256>>>(x, use_x, cin[l], Cs[l], Os[l], Wm[l]);
        agg_kernel <<<(NPK*Os[l])/256, 256>>>(Os[l], osh[l], coff[l], Gm[l], Bm[l]);
    }
    y5_kernel <<<dim3(NPK/128, 1024/128), 256, Y5_SMEM>>>(W5, g5, b5);
    fin_kernel<<<(NB*1024)/256, 256>>>(out);
    rep_kernel<<<(NB*2048*(NP/4))/256, 256>>>(out);
    seg_kernel<<<dim3(NP/32, 512/32, NB), dim3(32, 8)>>>(out);
}

// round 10
// speedup vs baseline: 1.7202x; 1.3545x over previous
#include <cuda_runtime.h>
#include <cstdint>

#define NB   8
#define NP   2048
#define KNN  10
#define NPK  (NB*NP)
#define BN_SC 0.9999950000374997f   // 1/sqrt(1+1e-5)

typedef unsigned long long u64;

// ---------------- scratch (static device globals; no allocations) ----------
__device__ float g_D [(size_t)4*NP*NP];      // 67 MB: 4-batch chunk, L2-resident
__device__ float g_XC[(size_t)NPK*512];      // concat(x1,x2,x3,x4) point-major
__device__ float g_P [(size_t)NPK*256];      // W_A · x   (per point)
__device__ float g_Q [(size_t)NPK*256];      // (W_B-W_A) · x
__device__ float g_xx[NPK];                  // squared norms
__device__ int   g_idx[NPK*KNN];             // knn indices
__device__ float g_pmax[16*NB*1024];         // per-128pt-block partial max of y5
__device__ float g_psum[16*NB*1024];         // per-128pt-block partial sum of y5
__device__ float g_glob[NB*2048];            // [gmax | gavg]

__device__ __forceinline__ const float* feat_ptr(const float* xext, int use_x,
                                                 int cin_off, int& ld) {
    if (use_x) { ld = 3; return xext; }
    ld = 512; return g_XC + cin_off;
}

__device__ __forceinline__ float lrelu(float y) { return y >= 0.f ? y : 0.2f*y; }
__device__ __forceinline__ float f2lo(u64 v) { return __uint_as_float((uint32_t)v); }
__device__ __forceinline__ float f2hi(u64 v) { return __uint_as_float((uint32_t)(v >> 32)); }

// float -> order-preserving uint (bigger float => bigger uint)
__device__ __forceinline__ uint32_t ordu(float v) {
    uint32_t u = __float_as_uint(v);
    return u ^ (uint32_t)(((int32_t)u >> 31) | 0x80000000);
}
__device__ __forceinline__ float unordu(uint32_t o) {
    uint32_t u = o ^ (uint32_t)((((int32_t)(~o)) >> 31) | 0x80000000);
    return __uint_as_float(u);
}
__device__ __forceinline__ u64 make_key(float v, int id) {
    return ((u64)ordu(v) << 32) | (uint32_t)(0xFFFFFFFFu - (uint32_t)id);
}
// branch-light insert into descending-sorted keys[KNN]
#define KEY_INSERT(keys, k)                                                   \
    if ((k) > keys[KNN-1]) {                                                  \
        keys[KNN-1] = (k);                                                    \
        _Pragma("unroll")                                                     \
        for (int _t = KNN-1; _t >= 1; _t--) {                                 \
            u64 _a = keys[_t-1], _b = keys[_t];                               \
            bool _sw = _b > _a;                                               \
            keys[_t-1] = _sw ? _b : _a;                                       \
            keys[_t]   = _sw ? _a : _b;                                       \
        }                                                                     \
    }

// packed-f32x2 8x8 micro-step on [16][128] smem panels.
#define GSTEP2(pA, pB, k)                                                     \
    {                                                                         \
        float4 a0 = *(const float4*)((pA) + (k)*128 + (ty << 2));             \
        float4 a1 = *(const float4*)((pA) + (k)*128 + 64 + (ty << 2));        \
        ulonglong2 bx = *(const ulonglong2*)((pB) + (k)*128 + (tx << 2));     \
        ulonglong2 by = *(const ulonglong2*)((pB) + (k)*128 + 64 + (tx << 2));\
        u64 bp[4] = {bx.x, bx.y, by.x, by.y};                                 \
        float av[8] = {a0.x,a0.y,a0.z,a0.w,a1.x,a1.y,a1.z,a1.w};              \
        _Pragma("unroll")                                                     \
        for (int p = 0; p < 8; p++) {                                         \
            u64 ad;                                                           \
            asm("mov.b64 %0, {%1, %1};" : "=l"(ad) : "r"(__float_as_uint(av[p]))); \
            _Pragma("unroll")                                                 \
            for (int q = 0; q < 4; q++)                                       \
                asm("fma.rn.f32x2 %0, %1, %2, %0;"                            \
                    : "+l"(acc2[p][q]) : "l"(ad), "l"(bp[q]));                \
        }                                                                     \
    }

// stage one 16x128 A-panel + 16x128 B-panel from float4 regs
#define STAGE(As, Bs)                                                         \
    {                                                                         \
        (As)[(kq4+0)*128+m0]=pa0.x; (As)[(kq4+1)*128+m0]=pa0.y;               \
        (As)[(kq4+2)*128+m0]=pa0.z; (As)[(kq4+3)*128+m0]=pa0.w;               \
        (Bs)[(kq4+0)*128+m0]=pb0.x; (Bs)[(kq4+1)*128+m0]=pb0.y;               \
        (Bs)[(kq4+2)*128+m0]=pb0.z; (Bs)[(kq4+3)*128+m0]=pb0.w;               \
        (As)[(kq4+0)*128+m1]=pa1.x; (As)[(kq4+1)*128+m1]=pa1.y;               \
        (As)[(kq4+2)*128+m1]=pa1.z; (As)[(kq4+3)*128+m1]=pa1.w;               \
        (Bs)[(kq4+0)*128+m1]=pb1.x; (Bs)[(kq4+1)*128+m1]=pb1.y;               \
        (Bs)[(kq4+2)*128+m1]=pb1.z; (Bs)[(kq4+3)*128+m1]=pb1.w;               \
    }

#define EPS 133   // staging stride (floats); scalar reads only, no alignment need

// ---------------- profiling-slot shim ---------------------------------------
__global__ void nop_kernel() {}

// ---------------- squared norms --------------------------------------------
__global__ void sq_kernel(const float* __restrict__ xext, int use_x, int cin_off, int C) {
    int pt = blockIdx.x*blockDim.x + threadIdx.x;
    if (pt >= NPK) return;
    int ld; const float* F = feat_ptr(xext, use_x, cin_off, ld);
    const float* r = F + (size_t)pt*ld;
    float s = 0.f;
    for (int c = 0; c < C; c++) { float v = r[c]; s = fmaf(v, v, s); }
    g_xx[pt] = s;
}

// ---------------- dist GEMM (symmetric, upper-tri blocks) -> D tiles --------
__global__ __launch_bounds__(256, 2)
void dist_kernel(const float* __restrict__ xext, int use_x, int cin_off, int C,
                 int cbase) {
    extern __shared__ float sm[];
    int bi = blockIdx.y, bj = blockIdx.x;
    if (bj < bi) return;                 // symmetry: skip lower triangle
    int ld; const float* F = feat_ptr(xext, use_x, cin_off, ld);
    int z = blockIdx.z;                  // batch within chunk
    int b = cbase + z;                   // global batch
    int i0 = bi << 7, j0 = bj << 7;
    int tid = threadIdx.x, tx = tid & 15, ty = tid >> 4;
    const float* Fb = F + (size_t)b*NP*ld;
    u64 acc2[8][4];
    #pragma unroll
    for (int p = 0; p < 8; p++)
        #pragma unroll
        for (int q = 0; q < 4; q++) acc2[p][q] = 0ull;

    if (((ld & 3) == 0) && ((C & 15) == 0)) {
        int nch = C >> 4;
        int m0 = tid >> 2, kq4 = (tid & 3) << 2;
        int m1 = m0 + 64;
        const float* Ar0 = &Fb[(size_t)(i0 + m0)*ld];
        const float* Br0 = &Fb[(size_t)(j0 + m0)*ld];
        const float* Ar1 = &Fb[(size_t)(i0 + m1)*ld];
        const float* Br1 = &Fb[(size_t)(j0 + m1)*ld];
        float4 pa0 = *(const float4*)(Ar0 + kq4);
        float4 pb0 = *(const float4*)(Br0 + kq4);
        float4 pa1 = *(const float4*)(Ar1 + kq4);
        float4 pb1 = *(const float4*)(Br1 + kq4);
        STAGE(sm, sm + 2048)
        for (int ch = 0; ch < nch; ch++) {
            if (ch + 1 < nch) {
                int c0 = (ch + 1) << 4;
                pa0 = *(const float4*)(Ar0 + c0 + kq4);
                pb0 = *(const float4*)(Br0 + c0 + kq4);
                pa1 = *(const float4*)(Ar1 + c0 + kq4);
                pb1 = *(const float4*)(Br1 + c0 + kq4);
            }
            __syncthreads();
            float* As = sm + (ch & 1)*4096;
            float* Bs = As + 2048;
            #pragma unroll
            for (int k = 0; k < 16; k++) GSTEP2(As, Bs, k)
            if (ch + 1 < nch) {
                float* Ad = sm + ((ch & 1) ^ 1)*4096;
                float* Bd = Ad + 2048;
                STAGE(Ad, Bd)
            }
        }
    } else {
        float* As = sm;
        float* Bs = sm + 2048;
        for (int c0 = 0; c0 < C; c0 += 16) {
            #pragma unroll
            for (int e = tid; e < 2048; e += 256) {
                int m = e >> 4, k = e & 15;
                float va = 0.f, vb = 0.f;
                if (c0 + k < C) {
                    va = Fb[(size_t)(i0 + m)*ld + c0 + k];
                    vb = Fb[(size_t)(j0 + m)*ld + c0 + k];
                }
                As[k*128+m] = va; Bs[k*128+m] = vb;
            }
            __syncthreads();
            #pragma unroll
            for (int k = 0; k < 16; k++) GSTEP2(As, Bs, k)
            __syncthreads();
        }
    }

    const float* xxb = g_xx + b*NP;
    float xi[8], xj[8];
    #pragma unroll
    for (int p = 0; p < 8; p++) {
        int r = (p < 4) ? ((ty << 2) + p) : (64 + (ty << 2) + p - 4);
        xi[p] = xxb[i0 + r];
    }
    #pragma unroll
    for (int q = 0; q < 8; q++) {
        int c = (q < 4) ? ((tx << 2) + q) : (64 + (tx << 2) + q - 4);
        xj[q] = xxb[j0 + c];
    }

    float* ep = sm;                      // 64 x EPS staging
    float* Db = g_D + (size_t)z*NP*NP;

    for (int pass = 0; pass < 2; pass++) {
        __syncthreads();
        #pragma unroll
        for (int p = 0; p < 4; p++) {
            int pp = pass*4 + p;
            int r  = (ty << 2) + p;
            float aq[8];
            aq[0] = f2lo(acc2[pp][0]); aq[1] = f2hi(acc2[pp][0]);
            aq[2] = f2lo(acc2[pp][1]); aq[3] = f2hi(acc2[pp][1]);
            aq[4] = f2lo(acc2[pp][2]); aq[5] = f2hi(acc2[pp][2]);
            aq[6] = f2lo(acc2[pp][3]); aq[7] = f2hi(acc2[pp][3]);
            #pragma unroll
            for (int q = 0; q < 4; q++)
                ep[r*EPS + (tx << 2) + q]      = 2.f*aq[q]   - xi[pp] - xj[q];
            #pragma unroll
            for (int q = 0; q < 4; q++)
                ep[r*EPS + 64 + (tx << 2) + q] = 2.f*aq[q+4] - xi[pp] - xj[q+4];
        }
        __syncthreads();

        int rowbase = i0 + pass*64;
        // direct (i,j) rows: 64 rows x 128 cols, coalesced float4 stores
        #pragma unroll
        for (int k = 0; k < 8; k++) {
            int f = k*256 + tid;
            int r = f >> 5, c4 = (f & 31) << 2;
            const float* s = ep + r*EPS + c4;
            float4 v = make_float4(s[0], s[1], s[2], s[3]);
            *(float4*)&Db[(size_t)(rowbase + r)*NP + j0 + c4] = v;
        }
        // mirrored (j,i) block half (transposed), skip on diagonal blocks
        if (bi != bj) {
            #pragma unroll
            for (int k = 0; k < 8; k++) {
                int f = k*256 + tid;
                int c = f >> 4, r4 = (f & 15) << 2;
                float4 v = make_float4(ep[(r4+0)*EPS + c], ep[(r4+1)*EPS + c],
                                       ep[(r4+2)*EPS + c], ep[(r4+3)*EPS + c]);
                *(float4*)&Db[(size_t)(j0 + c)*NP + rowbase + r4] = v;
            }
        }
    }
}

// ---------------- top-10 per row: warp-uniform threshold scan ---------------
// Pass 1: lane max over its 64 elems; 10 rounds of warp-max+disable give a
// conservative threshold (>=10 elements exceed it). Pass 2: ballot-gated
// broadcast inserts, replicated in all lanes (fully convergent).
__global__ __launch_bounds__(256)
void topk_kernel(int cbase) {
    int lane = threadIdx.x & 31, w = threadIdx.x >> 5;
    int rl = (blockIdx.x << 3) + w;                 // row within chunk
    const float4* dr = (const float4*)(g_D + (size_t)rl*NP);
    const float NEG_INF = __int_as_float(0xff800000);

    float lmax = NEG_INF;
    #pragma unroll 4
    for (int g = 0; g < 16; g++) {
        float4 v = dr[lane + (g << 5)];
        lmax = fmaxf(lmax, fmaxf(fmaxf(v.x, v.y), fmaxf(v.z, v.w)));
    }
    float cur = lmax, thrf = lmax;
    #pragma unroll
    for (int r = 0; r < KNN; r++) {
        float m = cur;
        #pragma unroll
        for (int off = 16; off > 0; off >>= 1)
            m = fmaxf(m, __shfl_xor_sync(0xffffffffu, m, off));
        thrf = m;
        if (cur == m) cur = NEG_INF;
    }

    u64 keys[KNN];
    #pragma unroll
    for (int t = 0; t < KNN; t++) keys[t] = 0ull;
    for (int g = 0; g < 16; g++) {
        float4 v = dr[lane + (g << 5)];
        float gm = fmaxf(fmaxf(v.x, v.y), fmaxf(v.z, v.w));
        unsigned mask = __ballot_sync(0xffffffffu, gm >= thrf);
        while (mask) {
            int src = __ffs(mask) - 1; mask &= mask - 1;
            float f0 = __shfl_sync(0xffffffffu, v.x, src);
            float f1 = __shfl_sync(0xffffffffu, v.y, src);
            float f2 = __shfl_sync(0xffffffffu, v.z, src);
            float f3 = __shfl_sync(0xffffffffu, v.w, src);
            int jb = (src + (g << 5)) << 2;
            float ff[4] = {f0, f1, f2, f3};
            #pragma unroll
            for (int e = 0; e < 4; e++) {
                if (ff[e] >= thrf) {
                    u64 k = make_key(ff[e], jb + e);
                    KEY_INSERT(keys, k)
                }
            }
            uint32_t ho = (uint32_t)(keys[KNN-1] >> 32);
            if (ho) thrf = fmaxf(thrf, unordu(ho));
        }
    }
    if (lane == 0) {
        int bl = rl >> 11;
        size_t grow = ((size_t)(cbase + bl)*NP + (rl & (NP-1)))*KNN;
        #pragma unroll
        for (int t = 0; t < KNN; t++)
            g_idx[grow + t] = (int)(0xFFFFFFFFu - (uint32_t)keys[t]);
    }
}

// ---------------- P/Q GEMM: P = X·W_A^T, Q = X·(W_B-W_A)^T ------------------
__global__ void pq_kernel(const float* __restrict__ xext, int use_x, int cin_off,
                          int C, int O, const float* __restrict__ W) {
    __shared__ float Fs [32][64];
    __shared__ float W1s[32][64];
    __shared__ float Wds[32][64];
    int ld; const float* F = feat_ptr(xext, use_x, cin_off, ld);
    int pt0 = blockIdx.x << 6, o0 = blockIdx.y << 6;
    int tid = threadIdx.x, tx = tid & 15, ty = tid >> 4;
    int twoC = 2*C;
    float accP[4][4], accQ[4][4];
    #pragma unroll
    for (int p = 0; p < 4; p++)
        #pragma unroll
        for (int q = 0; q < 4; q++) { accP[p][q] = 0.f; accQ[p][q] = 0.f; }

    for (int c0 = 0; c0 < C; c0 += 32) {
        #pragma unroll
        for (int e = tid; e < 2048; e += 256) {
            int c = e & 31, r = e >> 5;
            float f = 0.f, w1 = 0.f, wd = 0.f;
            if (c0 + c < C) {
                f  = F[(size_t)(pt0 + r)*ld + c0 + c];
                w1 = W[(size_t)(o0 + r)*twoC + c0 + c];
                wd = W[(size_t)(o0 + r)*twoC + C + c0 + c] - w1;
            }
            Fs[c][r] = f; W1s[c][r] = w1; Wds[c][r] = wd;
        }
        __syncthreads();
        int kc = C - c0; if (kc > 32) kc = 32;
        for (int c = 0; c < kc; c++) {
            float4 a4  = *(const float4*)&Fs [c][ty << 2];
            float4 w14 = *(const float4*)&W1s[c][tx << 2];
            float4 wd4 = *(const float4*)&Wds[c][tx << 2];
            float av [4] = {a4.x, a4.y, a4.z, a4.w};
            float w1v[4] = {w14.x, w14.y, w14.z, w14.w};
            float wdv[4] = {wd4.x, wd4.y, wd4.z, wd4.w};
            #pragma unroll
            for (int p = 0; p < 4; p++)
                #pragma unroll
                for (int q = 0; q < 4; q++) {
                    accP[p][q] = fmaf(av[p], w1v[q], accP[p][q]);
                    accQ[p][q] = fmaf(av[p], wdv[q], accQ[p][q]);
                }
        }
        __syncthreads();
    }
    #pragma unroll
    for (int p = 0; p < 4; p++) {
        size_t ro = (size_t)(pt0 + (ty << 2) + p)*O + o0 + (tx << 2);
        float4 pp = make_float4(accP[p][0], accP[p][1], accP[p][2], accP[p][3]);
        float4 qq = make_float4(accQ[p][0], accQ[p][1], accQ[p][2], accQ[p][3]);
        *(float4*)&g_P[ro] = pp;
        *(float4*)&g_Q[ro] = qq;
    }
}

// ---------------- gather + BN + LeakyReLU + max over k ----------------------
__global__ void agg_kernel(int O, int oshift, int coff, const float* __restrict__ g,
                           const float* __restrict__ bs) {
    int G = 256 >> oshift;                 // points per block
    int pt0 = blockIdx.x * G;
    int pi = threadIdx.x >> oshift;
    int o  = threadIdx.x & (O - 1);
    __shared__ int sj[4*KNN];
    if (threadIdx.x < G*KNN) sj[threadIdx.x] = g_idx[pt0*KNN + threadIdx.x];
    __syncthreads();
    int pt = pt0 + pi;
    int b  = pt >> 11;
    float q  = g_Q[(size_t)pt*O + o];
    float s  = g[o]*BN_SC, bb = bs[o];
    float m  = __int_as_float(0xff800000);
    const float* Pb = g_P + (size_t)b*NP*O;
    #pragma unroll
    for (int t = 0; t < KNN; t++) {
        float y = fmaf(Pb[(size_t)sj[pi*KNN + t]*O + o] + q, s, bb);
        m = fmaxf(m, lrelu(y));
    }
    g_XC[(size_t)pt*512 + coff + o] = m;
}

// ---------------- y5 GEMM (128x128x512, single-sync pipeline, f32x2) --------
__global__ __launch_bounds__(256, 2)
void y5_kernel(const float* __restrict__ W5, const float* __restrict__ g5,
               const float* __restrict__ b5) {
    extern __shared__ float sm[];
    int pt0 = blockIdx.x << 7, e0 = blockIdx.y << 7;
    int b   = pt0 >> 11;
    int pb  = (pt0 & (NP-1)) >> 7;
    int tid = threadIdx.x, tx = tid & 15, ty = tid >> 4;
    u64 acc2[8][4];
    #pragma unroll
    for (int p = 0; p < 8; p++)
        #pragma unroll
        for (int q = 0; q < 4; q++) acc2[p][q] = 0ull;

    int m0 = tid >> 2, kq4 = (tid & 3) << 2;
    int m1 = m0 + 64;
    const float* Ar0 = &g_XC[(size_t)(pt0 + m0)*512];
    const float* Br0 = &W5 [(size_t)(e0  + m0)*512];
    const float* Ar1 = &g_XC[(size_t)(pt0 + m1)*512];
    const float* Br1 = &W5 [(size_t)(e0  + m1)*512];
    float4 pa0 = *(const float4*)(Ar0 + kq4);
    float4 pb0 = *(const float4*)(Br0 + kq4);
    float4 pa1 = *(const float4*)(Ar1 + kq4);
    float4 pb1 = *(const float4*)(Br1 + kq4);
    STAGE(sm, sm + 2048)
    for (int ch = 0; ch < 32; ch++) {
        if (ch + 1 < 32) {
            int c0 = (ch + 1) << 4;
            pa0 = *(const float4*)(Ar0 + c0 + kq4);
            pb0 = *(const float4*)(Br0 + c0 + kq4);
            pa1 = *(const float4*)(Ar1 + c0 + kq4);
            pb1 = *(const float4*)(Br1 + c0 + kq4);
        }
        __syncthreads();
        float* As = sm + (ch & 1)*4096;
        float* Bs = As + 2048;
        #pragma unroll
        for (int k = 0; k < 16; k++) GSTEP2(As, Bs, k)
        if (ch + 1 < 32) {
            float* Ad = sm + ((ch & 1) ^ 1)*4096;
            float* Bd = Ad + 2048;
            STAGE(Ad, Bd)
        }
    }
    __syncthreads();

    float* smax = sm;
    float* ssum = sm + 2048;
    const float NEG_INF = __int_as_float(0xff800000);
    float sq[8], bq[8], mxv[8], smv[8];
    #pragma unroll
    for (int q = 0; q < 8; q++) {
        int c = (q < 4) ? ((tx << 2) + q) : (64 + (tx << 2) + q - 4);
        sq[q] = g5[e0 + c]*BN_SC; bq[q] = b5[e0 + c];
        mxv[q] = NEG_INF; smv[q] = 0.f;
    }
    #pragma unroll
    for (int p = 0; p < 8; p++) {
        float aq[8];
        aq[0] = f2lo(acc2[p][0]); aq[1] = f2hi(acc2[p][0]);
        aq[2] = f2lo(acc2[p][1]); aq[3] = f2hi(acc2[p][1]);
        aq[4] = f2lo(acc2[p][2]); aq[5] = f2hi(acc2[p][2]);
        aq[6] = f2lo(acc2[p][3]); aq[7] = f2hi(acc2[p][3]);
        #pragma unroll
        for (int q = 0; q < 8; q++) {
            float y = lrelu(fmaf(aq[q], sq[q], bq[q]));
            mxv[q] = fmaxf(mxv[q], y); smv[q] += y;
        }
    }
    #pragma unroll
    for (int q = 0; q < 8; q++) {
        int c = (q < 4) ? ((tx << 2) + q) : (64 + (tx << 2) + q - 4);
        smax[ty*128 + c] = mxv[q]; ssum[ty*128 + c] = smv[q];
    }
    __syncthreads();
    if (ty == 0) {
        #pragma unroll
        for (int q = 0; q < 8; q++) {
            int c = (q < 4) ? ((tx << 2) + q) : (64 + (tx << 2) + q - 4);
            float mx = NEG_INF, sv = 0.f;
            #pragma unroll
            for (int r = 0; r < 16; r++) {
                mx = fmaxf(mx, smax[r*128 + c]);
                sv += ssum[r*128 + c];
            }
            int gi = b*1024 + e0 + c;
            g_pmax[pb*(NB*1024) + gi] = mx;
            g_psum[pb*(NB*1024) + gi] = sv;
        }
    }
}

// ---------------- deterministic final reduction + glob writeout -------------
__global__ void fin_kernel(float* __restrict__ out) {
    int t = blockIdx.x*blockDim.x + threadIdx.x;
    if (t >= NB*1024) return;
    int b = t >> 10, e = t & 1023;
    float mx = __int_as_float(0xff800000), sm = 0.f;
    for (int pb = 0; pb < 16; pb++) {
        mx = fmaxf(mx, g_pmax[pb*(NB*1024) + t]);
        sm += g_psum[pb*(NB*1024) + t];
    }
    float av = sm*(1.0f/NP);
    g_glob[b*2048 + e]        = mx;
    g_glob[b*2048 + 1024 + e] = av;
    size_t off = (size_t)NB*2560*NP;
    out[off + b*2048 + e]        = mx;
    out[off + b*2048 + 1024 + e] = av;
}

// ---------------- broadcast glob into x_seg channels [0,2048) ---------------
__global__ void rep_kernel(float* __restrict__ out) {
    int lin = blockIdx.x*blockDim.x + threadIdx.x;
    int n4 = lin & 511;
    int ch = (lin >> 9) & 2047;
    int b  = lin >> 20;
    float v = g_glob[b*2048 + ch];
    float4 vv = make_float4(v, v, v, v);
    *(float4*)(out + ((size_t)(b*2560 + ch))*NP + (n4 << 2)) = vv;
}

// ---------------- transpose XC (B,N,512) -> x_seg channels [2048,2560) ------
__global__ void seg_kernel(float* __restrict__ out) {
    __shared__ float t[32][33];
    int b  = blockIdx.z;
    int c0 = blockIdx.y << 5;
    int n0 = blockIdx.x << 5;
    int tx = threadIdx.x, ty = threadIdx.y;
    #pragma unroll
    for (int r = ty; r < 32; r += 8)
        t[r][tx] = g_XC[((size_t)b*NP + n0 + r)*512 + c0 + tx];
    __syncthreads();
    #pragma unroll
    for (int r = ty; r < 32; r += 8)
        out[((size_t)(b*2560 + 2048 + c0 + r))*NP + n0 + tx] = t[tx][r];
}

// ---------------- driver -----------------------------------------------------
extern "C" void kernel_launch(void* const* d_in, const int* in_sizes, int n_in,
                              void* d_out, int out_size) {
    const float* x  = (const float*)d_in[0];
    const float* Wm[4] = {(const float*)d_in[2], (const float*)d_in[5],
                          (const float*)d_in[8], (const float*)d_in[11]};
    const float* Gm[4] = {(const float*)d_in[3], (const float*)d_in[6],
                          (const float*)d_in[9], (const float*)d_in[12]};
    const float* Bm[4] = {(const float*)d_in[4], (const float*)d_in[7],
                          (const float*)d_in[10], (const float*)d_in[13]};
    const float* W5 = (const float*)d_in[14];
    const float* g5 = (const float*)d_in[15];
    const float* b5 = (const float*)d_in[16];
    float* out = (float*)d_out;

    const int Cs[4]   = {3, 64, 64, 128};
    const int Os[4]   = {64, 64, 128, 256};
    const int osh[4]  = {6, 6, 7, 8};
    const int cin[4]  = {0, 0, 64, 128};
    const int coff[4] = {0, 64, 128, 256};

    const int DIST_SMEM = 8512*4;   // max(mainloop 8192, epilogue 64x133) floats
    const int Y5_SMEM   = 8192*4;

    for (int l = 0; l < 4; l++) {
        int use_x = (l == 0) ? 1 : 0;
        sq_kernel<<<NPK/256, 256>>>(x, use_x, cin[l], Cs[l]);
        if (l == 0) nop_kernel<<<1, 32>>>();   // profiled slot -> topk_c0(l0)
        for (int c = 0; c < 2; c++) {
            int cbase = c*4;
            dist_kernel<<<dim3(NP/128, NP/128, 4), 256, DIST_SMEM>>>(
                x, use_x, cin[l], Cs[l], cbase);
            topk_kernel<<<(4*NP)/8, 256>>>(cbase);
        }
        pq_kernel <<<dim3(NPK/64, Os[l]/64), 256>>>(x, use_x, cin[l], Cs[l], Os[l], Wm[l]);
        agg_kernel<<<(NPK*Os[l])/256, 256>>>(Os[l], osh[l], coff[l], Gm[l], Bm[l]);
    }
    y5_kernel <<<dim3(NPK/128, 1024/128), 256, Y5_SMEM>>>(W5, g5, b5);
    fin_kernel<<<(NB*1024)/256, 256>>>(out);
    rep_kernel<<<(NB*2048*(NP/4))/256, 256>>>(out);
    seg_kernel<<<dim3(NP/32, 512/32, NB), dim3(32, 8)>>>(out);
}